// round 15
// baseline (speedup 1.0000x reference)
#include <cuda_runtime.h>
#include <cuda_fp16.h>

#define N_ 10000
#define NPAD 10112
#define E_ 160000

typedef unsigned int uint32;

// ---------------- device scratch ---------------------------------------------
__device__ __align__(16) __half g_Qh[N_*256];
__device__ __align__(16) __half g_Kh[N_*256];
__device__ __align__(16) __half g_Vh[N_*256];
__device__ __align__(16) float g_score[E_*8];
__device__ __align__(16) __half g_xh[NPAD*256];
__device__ __align__(16) __half g_aggrh[NPAD*256];
__device__ __align__(16) __half g_x1h[NPAD*256];
__device__ __align__(16) __half g_ffn[NPAD*1024];
__device__ int   g_cnt[N_];
__device__ int   g_rowptr[N_+1];
__device__ int   g_cur[N_];
__device__ int   g_pos[E_];    // edge -> CSR slot
__device__ int   g_srcs[E_];   // CSR slot -> src node

// transposed weights, [N][K] fp16 (K contiguous)
#define OFF_Q  0u
#define OFF_K  65536u
#define OFF_V  131072u
#define OFF_P2 196608u
#define OFF_O  262144u
#define OFF_F1 327680u      /* [1024][256] */
#define OFF_F2 589824u      /* [256][1024] */
#define WT_TOTAL 851968u
__device__ __align__(16) __half g_wt[WT_TOTAL];

// ---------------- smem layouts ---------------------------------------------------
// QKV/FFN1 (M=128,N=128): 3-stage A + 3-stage B
#define QA(i)  ((i)*16384)
#define QB(i)  (49152 + (i)*16384)
#define Q_PAR  98304
#define Q_DYN  100352
// LN (M=64,N=256): 2-stage
#define L_A0 0
#define L_A1 8192
#define L_B0 16384
#define L_B1 49152
#define L_PAR 81920
#define L_DYN 94208
// EDGE (M=64,N=256): full A (4 chunks) + 2 B buffers
#define EA    0          /* 4 x 8192 = 32768 */
#define EB0   32768
#define EB1   65536
#define E_PAR 98304
#define E_DYN 110592

__device__ __forceinline__ uint32 smem_to_u32(const void* p){
  uint32 a;
  asm("{ .reg .u64 t; cvta.to.shared.u64 t, %1; cvt.u32.u64 %0, t; }" : "=r"(a) : "l"(p));
  return a;
}
__device__ __forceinline__ uint32 swz(int row, int c16){
  return (uint32)(row*128 + (((c16) ^ (row & 7)) << 4));
}
__device__ __forceinline__ void ldsm4(uint32* r, uint32 addr){
  asm volatile("ldmatrix.sync.aligned.m8n8.x4.shared.b16 {%0,%1,%2,%3}, [%4];"
    : "=r"(r[0]),"=r"(r[1]),"=r"(r[2]),"=r"(r[3]) : "r"(addr));
}
__device__ __forceinline__ void mma_f16(float* c, const uint32* a, uint32 b0, uint32 b1){
  asm volatile("mma.sync.aligned.m16n8k16.row.col.f32.f16.f16.f32 "
    "{%0,%1,%2,%3}, {%4,%5,%6,%7}, {%8,%9}, {%0,%1,%2,%3};"
    : "+f"(c[0]),"+f"(c[1]),"+f"(c[2]),"+f"(c[3])
    : "r"(a[0]),"r"(a[1]),"r"(a[2]),"r"(a[3]), "r"(b0),"r"(b1));
}
__device__ __forceinline__ void cpa16(uint32 dst, const void* src){
  asm volatile("cp.async.cg.shared.global [%0], [%1], 16;" :: "r"(dst), "l"(src));
}
#define CPA_COMMIT() asm volatile("cp.async.commit_group;" ::: "memory")
#define CPA_WAIT(n)  asm volatile("cp.async.wait_group %0;" :: "n"(n) : "memory")

union HU { __half h[8]; uint4 u; };

// ---------------- staging: fp16 tile via cp.async -------------------------------
template<int ROWS>
__device__ __forceinline__ void stage_tile(uint32 dstbase, const __half* src0,
                                           int Kst, int kk, int t){
  #pragma unroll
  for (int s=0; s<(ROWS>>5); s++){
    int slot = t + s*256;
    int r = slot >> 3, g = slot & 7;
    cpa16(dstbase + swz(r, g), (const void*)(src0 + (size_t)r*Kst + kk + g*8));
  }
}

// ---------------- warp MMA mainloop: warp tile 32 x 64 --------------------------
__device__ __forceinline__ void compute_chunk(uint32 sb, uint32 aoff, uint32 boff,
                                              int lane, int wm, int wn,
                                              float (&acc)[2][8][4]){
  uint32 rbA[2]; int rxA[2];
  #pragma unroll
  for (int mi=0;mi<2;mi++){
    int row = wm*32 + mi*16 + (lane&15);
    rbA[mi] = sb + aoff + row*128;
    rxA[mi] = row & 7;
  }
  int hi4 = lane>>4;
  uint32 rbB[4]; int rxB[4];
  #pragma unroll
  for (int g=0; g<4; g++){
    int n = wn*64 + g*16 + ((lane>>4)<<3) + (lane&7);
    rbB[g] = sb + boff + n*128;
    rxB[g] = n & 7;
  }
  int cB = (lane>>3)&1;
  #pragma unroll
  for (int ks=0; ks<4; ks++){
    int c16 = ks*2;
    uint32 Ah[2][4];
    #pragma unroll
    for (int mi=0;mi<2;mi++){
      uint32 off = ((uint32)((c16 + hi4) ^ rxA[mi])) << 4;
      ldsm4(Ah[mi], rbA[mi] + off);
    }
    uint32 Bh[4][4];
    #pragma unroll
    for (int g=0; g<4; g++){
      uint32 off = ((uint32)((c16 + cB) ^ rxB[g])) << 4;
      ldsm4(Bh[g], rbB[g] + off);
    }
    #pragma unroll
    for (int mi=0;mi<2;mi++){
      #pragma unroll
      for (int nn=0;nn<8;nn++)
        mma_f16(acc[mi][nn], Ah[mi], Bh[nn>>1][(nn&1)*2], Bh[nn>>1][(nn&1)*2+1]);
    }
  }
}

#define ZERO_ACC(acc) { \
  _Pragma("unroll") for (int _a=0;_a<2;_a++) \
    _Pragma("unroll") for (int _b=0;_b<8;_b++) \
      _Pragma("unroll") for (int _c=0;_c<4;_c++) (acc)[_a][_b][_c]=0.f; }

// ---------------- CSR build (count fused into prep) -----------------------------
__global__ void k_scan(){
  __shared__ int sh[1024];
  int t = threadIdx.x;
  int base = t*10;
  int loc[10]; int run=0;
  #pragma unroll
  for (int i=0;i<10;i++){ int idx=base+i; int v=(idx<N_)? g_cnt[idx]:0; loc[i]=run; run+=v; }
  sh[t]=run; __syncthreads();
  for (int off=1; off<1024; off<<=1){
    int v = (t>=off)? sh[t-off] : 0;
    __syncthreads();
    sh[t] += v;
    __syncthreads();
  }
  int pre = (t>0)? sh[t-1] : 0;
  #pragma unroll
  for (int i=0;i<10;i++){ int idx=base+i; if (idx<N_){ int p=pre+loc[i]; g_rowptr[idx]=p; g_cur[idx]=p; } }
  if (t==1023) g_rowptr[N_] = sh[1023];
}
__global__ void k_scatter(const int* __restrict__ ei){
  int e = blockIdx.x*256+threadIdx.x;
  if (e<E_){
    int d = ei[E_+e];
    int p = atomicAdd(&g_cur[d], 1);
    g_pos[e] = p;
    g_srcs[p] = ei[e];
  }
  if (e<N_) g_cnt[e]=0;
}

// ---------------- fused prep: 7 weight transposes + x fp16 + edge count ---------
__global__ void k_prep_all(
    const float* __restrict__ Wq, const float* __restrict__ Wk,
    const float* __restrict__ Wv, const float* __restrict__ Wp2,
    const float* __restrict__ Wo, const float* __restrict__ Wf1,
    const float* __restrict__ Wf2, const float* __restrict__ x,
    const int* __restrict__ ei){
  __shared__ float tile[32][33];
  int bid = blockIdx.x;
  int tx = threadIdx.x, ty = threadIdx.y;   // 32 x 8
  int t = ty*32 + tx;
  if (bid >= 2082){
    int e = (bid-2082)*256 + t;
    if (e<E_) atomicAdd(&g_cnt[ei[E_+e]], 1);
    return;
  }
  if (bid >= 832){
    size_t base = (size_t)(bid-832)*2048 + (size_t)t*8;
    float4 a = *(const float4*)(x + base);
    float4 b = *(const float4*)(x + base + 4);
    HU H;
    H.h[0]=__float2half_rn(a.x); H.h[1]=__float2half_rn(a.y);
    H.h[2]=__float2half_rn(a.z); H.h[3]=__float2half_rn(a.w);
    H.h[4]=__float2half_rn(b.x); H.h[5]=__float2half_rn(b.y);
    H.h[6]=__float2half_rn(b.z); H.h[7]=__float2half_rn(b.w);
    *(uint4*)(g_xh + base) = H.u;
    return;
  }
  const float* W; int K, N; uint32 off; int local;
  if (bid < 320){
    local = bid & 63;
    int w = bid >> 6;
    W = (w==0)?Wq:(w==1)?Wk:(w==2)?Wv:(w==3)?Wp2:Wo;
    K = 256; N = 256; off = (uint32)w*65536u;
  } else if (bid < 576){ local = bid-320; W = Wf1; K = 256;  N = 1024; off = OFF_F1; }
  else                 { local = bid-576; W = Wf2; K = 1024; N = 256;  off = OFF_F2; }
  int nkb = K/32;
  int k0 = (local % nkb)*32, n0 = (local / nkb)*32;
  #pragma unroll
  for (int i=0;i<4;i++)
    tile[ty+i*8][tx] = W[(size_t)(k0+ty+i*8)*N + n0 + tx];
  __syncthreads();
  #pragma unroll
  for (int i=0;i<4;i++){
    int n = n0 + ty + i*8, k = k0 + tx;
    g_wt[(size_t)off + (size_t)n*K + k] = __float2half_rn(tile[tx][ty+i*8]);
  }
}

// ---------------- QKV GEMMs: M=128, N=128 tile; 3-stage, 1 sync/chunk -----------
__global__ void __launch_bounds__(256,2) k_mm_qkv(
    const float* __restrict__ bq, const float* __restrict__ bk,
    const float* __restrict__ bv){
  extern __shared__ char smem[];
  uint32 sb = smem_to_u32(smem);
  int t = threadIdx.x, lane = t&31, wid = t>>5;
  int wm = wid>>1, wn = wid&1;
  int r0 = blockIdx.x*128;
  int gemm = blockIdx.y >> 1, nh = blockIdx.y & 1;
  const __half* Bsrc = g_wt + (size_t)gemm*65536 + (size_t)nh*128*256;
  const float* bias = (gemm==0)?bq:((gemm==1)?bk:bv);
  __half* C = (gemm==0)?g_Qh:((gemm==1)?g_Kh:g_Vh);
  const __half* Asrc = g_xh + (size_t)r0*256;
  float* s_bias = (float*)(smem + Q_PAR);
  if (t < 128) s_bias[t] = bias[nh*128 + t];

  float acc[2][8][4];
  ZERO_ACC(acc);

  stage_tile<128>(sb + QA(0), Asrc, 256, 0, t);
  stage_tile<128>(sb + QB(0), Bsrc, 256, 0, t);
  CPA_COMMIT();
  stage_tile<128>(sb + QA(1), Asrc, 256, 64, t);
  stage_tile<128>(sb + QB(1), Bsrc, 256, 64, t);
  CPA_COMMIT();
  #pragma unroll
  for (int ck=0; ck<4; ck++){
    if (ck==3){ CPA_WAIT(0); } else { CPA_WAIT(1); }
    __syncthreads();
    if (ck+2 < 4){
      int b = (ck+2)%3;
      stage_tile<128>(sb + QA(b), Asrc, 256, (ck+2)*64, t);
      stage_tile<128>(sb + QB(b), Bsrc, 256, (ck+2)*64, t);
      CPA_COMMIT();
    }
    compute_chunk(sb, QA(ck%3), QB(ck%3), lane, wm, wn, acc);
  }

  #pragma unroll
  for (int mi=0;mi<2;mi++){
    int rA = wm*32 + mi*16 + (lane>>2);
    #pragma unroll
    for (int half=0; half<2; half++){
      int row = r0 + rA + half*8;
      if (row >= N_) continue;
      #pragma unroll
      for (int ni=0;ni<8;ni++){
        int lc = wn*64 + ni*8 + (lane&3)*2;
        float v0 = acc[mi][ni][half*2+0] + s_bias[lc];
        float v1 = acc[mi][ni][half*2+1] + s_bias[lc+1];
        *(__half2*)(C + (size_t)row*256 + nh*128 + lc) = __floats2half2_rn(v0, v1);
      }
    }
  }
}

// ---------------- FFN1: M=128, N=128 tile; 3-stage, 1 sync/chunk ----------------
__global__ void __launch_bounds__(256,2) k_mm_ffn1(const float* __restrict__ bf1){
  extern __shared__ char smem[];
  uint32 sb = smem_to_u32(smem);
  int t = threadIdx.x, lane = t&31, wid = t>>5;
  int wm = wid>>1, wn = wid&1;
  int r0 = blockIdx.x*128;
  int colOff = blockIdx.y*128;
  const __half* Bsrc = g_wt + OFF_F1 + (size_t)colOff*256;
  const __half* Asrc = g_x1h + (size_t)r0*256;
  float* s_bias = (float*)(smem + Q_PAR);
  if (t < 128) s_bias[t] = bf1[colOff + t];

  float acc[2][8][4];
  ZERO_ACC(acc);

  stage_tile<128>(sb + QA(0), Asrc, 256, 0, t);
  stage_tile<128>(sb + QB(0), Bsrc, 256, 0, t);
  CPA_COMMIT();
  stage_tile<128>(sb + QA(1), Asrc, 256, 64, t);
  stage_tile<128>(sb + QB(1), Bsrc, 256, 64, t);
  CPA_COMMIT();
  #pragma unroll
  for (int ck=0; ck<4; ck++){
    if (ck==3){ CPA_WAIT(0); } else { CPA_WAIT(1); }
    __syncthreads();
    if (ck+2 < 4){
      int b = (ck+2)%3;
      stage_tile<128>(sb + QA(b), Asrc, 256, (ck+2)*64, t);
      stage_tile<128>(sb + QB(b), Bsrc, 256, (ck+2)*64, t);
      CPA_COMMIT();
    }
    compute_chunk(sb, QA(ck%3), QB(ck%3), lane, wm, wn, acc);
  }

  #pragma unroll
  for (int mi=0;mi<2;mi++){
    int rA = wm*32 + mi*16 + (lane>>2);
    #pragma unroll
    for (int half=0; half<2; half++){
      int row = r0 + rA + half*8;
      if (row >= N_) continue;
      #pragma unroll
      for (int ni=0;ni<8;ni++){
        int lc = wn*64 + ni*8 + (lane&3)*2;
        float v0 = fmaxf(acc[mi][ni][half*2+0] + s_bias[lc],   0.f);
        float v1 = fmaxf(acc[mi][ni][half*2+1] + s_bias[lc+1], 0.f);
        *(__half2*)(g_ffn + (size_t)row*1024 + colOff + lc) = __floats2half2_rn(v0, v1);
      }
    }
  }
}

// ---------------- edge: M=64, N=256; full-A hoist; pe GEMM + LN + scores --------
__global__ void __launch_bounds__(256,2) k_mm_edge(
    const float* __restrict__ pos, const int* __restrict__ ei,
    const float* __restrict__ Wp1, const float* __restrict__ bp1,
    const float* __restrict__ bp2, const float* __restrict__ gp,
    const float* __restrict__ bpn){
  extern __shared__ char smem[];
  uint32 sb = smem_to_u32(smem);
  int t = threadIdx.x, lane = t&31, wid = t>>5;
  int wm = wid>>2, wn = wid&3;
  int e0 = blockIdx.x*64;

  float* s_w1   = (float*)(smem + E_PAR);   // 768
  float* s_b1   = s_w1 + 768;               // 256
  float* s_p2   = s_b1 + 256;               // 256
  float* s_gp   = s_p2 + 256;               // 256
  float* s_bn   = s_gp + 256;               // 256
  float* s_dp   = s_bn + 256;               // 192
  float* s_part = s_dp + 192;               // 512
  int*   s_nd   = (int*)(s_part + 512);     // 192 ints (src, dst, pos)

  // stage B chunk 0 first so it flies during param load + A generation
  stage_tile<256>(sb + EB0, g_wt + OFF_P2, 256, 0, t);
  CPA_COMMIT();

  s_w1[t]     = Wp1[t];
  s_w1[256+t] = Wp1[256+t];
  s_w1[512+t] = Wp1[512+t];
  s_b1[t] = bp1[t]; s_p2[t] = bp2[t]; s_gp[t] = gp[t]; s_bn[t] = bpn[t];
  if (t < 64){
    int e = e0 + t;
    int sn = ei[e], dn = ei[E_+e];
    s_nd[t] = sn; s_nd[64+t] = dn; s_nd[128+t] = g_pos[e];
    s_dp[t*3+0] = pos[dn*3+0]-pos[sn*3+0];
    s_dp[t*3+1] = pos[dn*3+1]-pos[sn*3+1];
    s_dp[t*3+2] = pos[dn*3+2]-pos[sn*3+2];
  }
  __syncthreads();

  int rr = t>>2, q4 = t&3;
  float dx = s_dp[rr*3+0], dy = s_dp[rr*3+1], dz = s_dp[rr*3+2];

  // generate ALL 4 A chunks up front (overlaps with B0 cp.async flight)
  #pragma unroll
  for (int ck=0; ck<4; ck++){
    int kk = ck*64;
    #pragma unroll
    for (int half=0; half<2; half++){
      HU H;
      #pragma unroll
      for (int j=0; j<8; j++){
        int c = kk + q4*16 + half*8 + j;
        float v = fmaf(dz, s_w1[512+c], fmaf(dy, s_w1[256+c], fmaf(dx, s_w1[c], s_b1[c])));
        H.h[j] = __float2half_rn(fmaxf(v, 0.f));
      }
      *(uint4*)(smem + EA + ck*8192 + swz(rr, q4*2 + half)) = H.u;
    }
  }

  float acc[2][8][4];
  ZERO_ACC(acc);

  #pragma unroll
  for (int ck=0; ck<4; ck++){
    if (ck<3){
      stage_tile<256>(sb + ((ck&1)? EB0:EB1), g_wt + OFF_P2, 256, (ck+1)*64, t);
      CPA_COMMIT(); CPA_WAIT(1);
    } else { CPA_WAIT(0); }
    __syncthreads();
    compute_chunk(sb, EA + ck*8192, (ck&1)?EB1:EB0, lane, wm, wn, acc);
    if (ck<3) __syncthreads();
  }

  // pass 1: vals = acc + bp2; per-row partial LN stats
  #pragma unroll
  for (int mi=0;mi<2;mi++){
    int rA = wm*32 + mi*16 + (lane>>2);
    #pragma unroll
    for (int half=0; half<2; half++){
      int rl = rA + half*8;
      float s1=0.f, s2=0.f;
      #pragma unroll
      for (int ni=0;ni<8;ni++){
        int col = wn*64 + ni*8 + (lane&3)*2;
        float v0 = acc[mi][ni][half*2+0] + s_p2[col];
        float v1 = acc[mi][ni][half*2+1] + s_p2[col+1];
        acc[mi][ni][half*2+0] = v0;
        acc[mi][ni][half*2+1] = v1;
        s1 += v0 + v1;
        s2 = fmaf(v0, v0, fmaf(v1, v1, s2));
      }
      s1 += __shfl_xor_sync(0xffffffffu, s1, 1);
      s1 += __shfl_xor_sync(0xffffffffu, s1, 2);
      s2 += __shfl_xor_sync(0xffffffffu, s2, 1);
      s2 += __shfl_xor_sync(0xffffffffu, s2, 2);
      if ((lane&3)==0){ s_part[(rl*4+wn)*2] = s1; s_part[(rl*4+wn)*2+1] = s2; }
    }
  }
  __syncthreads();

  // pass 2: LN + per-head scores (fp16 Q/K gathers)
  const float SC = 0.17677669529663688f;  // 1/sqrt(32)
  #pragma unroll
  for (int mi=0;mi<2;mi++){
    int rA = wm*32 + mi*16 + (lane>>2);
    #pragma unroll
    for (int half=0; half<2; half++){
      int rl = rA + half*8;
      float s1 = s_part[(rl*4+0)*2] + s_part[(rl*4+1)*2]
               + s_part[(rl*4+2)*2] + s_part[(rl*4+3)*2];
      float s2 = s_part[(rl*4+0)*2+1] + s_part[(rl*4+1)*2+1]
               + s_part[(rl*4+2)*2+1] + s_part[(rl*4+3)*2+1];
      float m = s1*(1.f/256.f);
      float rstd = rsqrtf(fmaxf(s2*(1.f/256.f) - m*m, 0.f) + 1e-5f);
      int sn = s_nd[rl], dn = s_nd[64+rl], pp = s_nd[128+rl];
      const __half* Qp = g_Qh + (size_t)dn*256;
      const __half* Kp = g_Kh + (size_t)sn*256;
      #pragma unroll
      for (int h=0; h<2; h++){
        float partial = 0.f;
        #pragma unroll
        for (int nio=0; nio<4; nio++){
          int ni = h*4 + nio;
          int col = wn*64 + ni*8 + (lane&3)*2;
          float2 qv = __half22float2(*(const __half2*)(Qp + col));
          float2 kv = __half22float2(*(const __half2*)(Kp + col));
          float pe0 = (acc[mi][ni][half*2+0]-m)*rstd*s_gp[col]   + s_bn[col];
          float pe1 = (acc[mi][ni][half*2+1]-m)*rstd*s_gp[col+1] + s_bn[col+1];
          partial = fmaf(qv.x, kv.x + pe0, partial);
          partial = fmaf(qv.y, kv.y + pe1, partial);
        }
        partial += __shfl_xor_sync(0xffffffffu, partial, 1);
        partial += __shfl_xor_sync(0xffffffffu, partial, 2);
        if ((lane&3)==0)
          g_score[(size_t)pp*8 + wn*2 + h] = partial*SC;
      }
    }
  }
}

// ---------------- segment softmax + weighted aggregation (128 thr, half2 V) -----
__global__ void __launch_bounds__(128) k_aggr(){
  int n = blockIdx.x;
  int beg = g_rowptr[n], end = g_rowptr[n+1];
  int t = threadIdx.x, lane = t&31, w = t>>5;   // 4 warps
  __shared__ float s_mx[8], s_rs[8];
  __shared__ float s_at[128*8];
  __shared__ int   s_sc[128];

  #pragma unroll
  for (int hh=0; hh<2; hh++){
    int h = w*2 + hh;
    float mx = -3.0e38f;
    for (int i=beg+lane; i<end; i+=32)
      mx = fmaxf(mx, g_score[(size_t)i*8+h]);
    #pragma unroll
    for (int o=16;o>0;o>>=1) mx = fmaxf(mx, __shfl_xor_sync(0xffffffffu, mx, o));
    float s=0.f;
    for (int i=beg+lane; i<end; i+=32)
      s += __expf(g_score[(size_t)i*8+h]-mx);
    #pragma unroll
    for (int o=16;o>0;o>>=1) s += __shfl_xor_sync(0xffffffffu, s, o);
    if (lane==0){ s_mx[h]=mx; s_rs[h]=1.f/(s+1e-16f); }
  }
  __syncthreads();

  float ax=0.f, ay=0.f;
  int c0col = t*2;
  int h = c0col >> 5;
  for (int c0=beg; c0<end; c0+=128){
    int cn = min(128, end-c0);
    for (int j=t; j<cn*8; j+=128){
      int i=j>>3, hh=j&7;
      s_at[i*8+hh] = __expf(g_score[(size_t)(c0+i)*8+hh]-s_mx[hh])*s_rs[hh];
      if (hh==0) s_sc[i] = g_srcs[c0+i];
    }
    __syncthreads();
    for (int i=0;i<cn;i++){
      float a = s_at[i*8+h];
      float2 v = __half22float2(*(const __half2*)(g_Vh + (size_t)s_sc[i]*256 + c0col));
      ax = fmaf(a, v.x, ax);
      ay = fmaf(a, v.y, ay);
    }
    __syncthreads();
  }
  *(__half2*)(g_aggrh + (size_t)n*256 + c0col) = __floats2half2_rn(ax, ay);
}

// ---------------- GEMM + LN (Wo / FFN2): M=64, N=256; fp16 residuals ------------
__global__ void __launch_bounds__(256,2) k_mm_ln(int mode,
    const float* __restrict__ bias,
    const float* __restrict__ gam, const float* __restrict__ bet,
    float* __restrict__ outp){
  extern __shared__ char smem[];
  uint32 sb = smem_to_u32(smem);
  int t = threadIdx.x, lane = t&31, wid = t>>5;
  int wm = wid>>2, wn = wid&3;
  int r0 = blockIdx.x*64;
  const __half* res; int K; const __half* Bsrc; const __half* Asrc; int Kst;
  if (mode==0){
    res = g_xh;  K=256;  Bsrc=g_wt+OFF_O;
    Asrc = g_aggrh + (size_t)r0*256; Kst=256;
  } else {
    res = g_x1h; K=1024; Bsrc=g_wt+OFF_F2;
    Asrc = g_ffn + (size_t)r0*1024; Kst=1024;
  }

  float* s_bias = (float*)(smem + L_PAR);
  float* s_g    = s_bias + 256;
  float* s_b    = s_g + 256;
  float* s_part = s_b + 256;
  s_bias[t] = bias[t]; s_g[t] = gam[t]; s_b[t] = bet[t];

  float acc[2][8][4];
  ZERO_ACC(acc);

  int nchunks = K/64;
  stage_tile<64>(sb + L_A0, Asrc, Kst, 0, t);
  stage_tile<256>(sb + L_B0, Bsrc, K, 0, t);
  CPA_COMMIT();
  for (int ck=0; ck<nchunks; ck++){
    if (ck+1 < nchunks){
      stage_tile<64>(sb + ((ck&1)? L_A0:L_A1), Asrc, Kst, (ck+1)*64, t);
      stage_tile<256>(sb + ((ck&1)? L_B0:L_B1), Bsrc, K, (ck+1)*64, t);
      CPA_COMMIT(); CPA_WAIT(1);
    } else { CPA_WAIT(0); }
    __syncthreads();
    compute_chunk(sb, (ck&1)?L_A1:L_A0, (ck&1)?L_B1:L_B0, lane, wm, wn, acc);
    if (ck+1 < nchunks) __syncthreads();
  }

  #pragma unroll
  for (int mi=0;mi<2;mi++){
    int rA = wm*32 + mi*16 + (lane>>2);
    #pragma unroll
    for (int half=0; half<2; half++){
      int rl = rA + half*8;
      int row = r0 + rl;
      bool ok = row < N_;
      float s1=0.f, s2=0.f;
      #pragma unroll
      for (int ni=0;ni<8;ni++){
        int col = wn*64 + ni*8 + (lane&3)*2;
        float2 rv = ok ? __half22float2(*(const __half2*)(res + (size_t)row*256 + col))
                       : make_float2(0.f, 0.f);
        float v0 = acc[mi][ni][half*2+0] + s_bias[col]   + rv.x;
        float v1 = acc[mi][ni][half*2+1] + s_bias[col+1] + rv.y;
        acc[mi][ni][half*2+0] = v0;
        acc[mi][ni][half*2+1] = v1;
        s1 += v0 + v1;
        s2 = fmaf(v0, v0, fmaf(v1, v1, s2));
      }
      s1 += __shfl_xor_sync(0xffffffffu, s1, 1);
      s1 += __shfl_xor_sync(0xffffffffu, s1, 2);
      s2 += __shfl_xor_sync(0xffffffffu, s2, 1);
      s2 += __shfl_xor_sync(0xffffffffu, s2, 2);
      if ((lane&3)==0){ s_part[(rl*4+wn)*2] = s1; s_part[(rl*4+wn)*2+1] = s2; }
    }
  }
  __syncthreads();

  #pragma unroll
  for (int mi=0;mi<2;mi++){
    int rA = wm*32 + mi*16 + (lane>>2);
    #pragma unroll
    for (int half=0; half<2; half++){
      int rl = rA + half*8;
      int row = r0 + rl;
      if (row >= N_) continue;
      float s1 = s_part[(rl*4+0)*2] + s_part[(rl*4+1)*2]
               + s_part[(rl*4+2)*2] + s_part[(rl*4+3)*2];
      float s2 = s_part[(rl*4+0)*2+1] + s_part[(rl*4+1)*2+1]
               + s_part[(rl*4+2)*2+1] + s_part[(rl*4+3)*2+1];
      float m = s1*(1.f/256.f);
      float rstd = rsqrtf(fmaxf(s2*(1.f/256.f) - m*m, 0.f) + 1e-5f);
      #pragma unroll
      for (int ni=0;ni<8;ni++){
        int col = wn*64 + ni*8 + (lane&3)*2;
        float o0 = (acc[mi][ni][half*2+0]-m)*rstd*s_g[col]   + s_b[col];
        float o1 = (acc[mi][ni][half*2+1]-m)*rstd*s_g[col+1] + s_b[col+1];
        if (mode==0){
          *(__half2*)(g_x1h + (size_t)row*256 + col) = __floats2half2_rn(o0, o1);
        } else {
          *(float2*)(outp + (size_t)row*256 + col) = make_float2(o0, o1);
        }
      }
    }
  }
}

// ---------------- launch ---------------------------------------------------------
extern "C" void kernel_launch(void* const* d_in, const int* in_sizes, int n_in,
                              void* d_out, int out_size){
  const float* x    = (const float*)d_in[0];
  const float* pos  = (const float*)d_in[1];
  const int*   ei   = (const int*)  d_in[2];
  const float* Wq   = (const float*)d_in[3];
  const float* bq   = (const float*)d_in[4];
  const float* Wk   = (const float*)d_in[5];
  const float* bk   = (const float*)d_in[6];
  const float* Wv   = (const float*)d_in[7];
  const float* bv   = (const float*)d_in[8];
  const float* Wp1  = (const float*)d_in[9];
  const float* bp1  = (const float*)d_in[10];
  const float* Wp2  = (const float*)d_in[11];
  const float* bp2  = (const float*)d_in[12];
  const float* gp   = (const float*)d_in[13];
  const float* bp   = (const float*)d_in[14];
  const float* Wo   = (const float*)d_in[15];
  const float* bo   = (const float*)d_in[16];
  const float* g1   = (const float*)d_in[17];
  const float* b1n  = (const float*)d_in[18];
  const float* Wf1  = (const float*)d_in[19];
  const float* bf1  = (const float*)d_in[20];
  const float* Wf2  = (const float*)d_in[21];
  const float* bf2  = (const float*)d_in[22];
  const float* g2   = (const float*)d_in[23];
  const float* b2n  = (const float*)d_in[24];
  float* out = (float*)d_out;

  cudaFuncSetAttribute(k_mm_qkv,  cudaFuncAttributeMaxDynamicSharedMemorySize, Q_DYN);
  cudaFuncSetAttribute(k_mm_ffn1, cudaFuncAttributeMaxDynamicSharedMemorySize, Q_DYN);
  cudaFuncSetAttribute(k_mm_edge, cudaFuncAttributeMaxDynamicSharedMemorySize, E_DYN);
  cudaFuncSetAttribute(k_mm_ln,   cudaFuncAttributeMaxDynamicSharedMemorySize, L_DYN);

  const int MT128 = (N_ + 127) / 128;  // 79
  const int MT64  = (N_ + 63) / 64;    // 157
  const int ET    = E_ / 64;           // 2500

  // fused prep: 7 weight transposes + x->fp16 + edge count
  k_prep_all<<<2707, dim3(32,8)>>>(Wq, Wk, Wv, Wp2, Wo, Wf1, Wf2, x, ei);

  // CSR: scan + scatter (g_cnt re-zeroed by k_scatter tail each run)
  k_scan   <<<1, 1024>>>();
  k_scatter<<<(E_+255)/256, 256>>>(ei);

  // Q/K/V  (3 gemms x 2 n-halves)  [fp16 out]
  k_mm_qkv<<<dim3(MT128,6), 256, Q_DYN>>>(bq, bk, bv);

  // edge: pe-MLP GEMM + LN + scores (CSR-ordered)
  k_mm_edge<<<ET, 256, E_DYN>>>(pos, ei, Wp1, bp1, bp2, gp, bp);

  // segment softmax + aggregation [fp16 out]
  k_aggr<<<N_, 128>>>();

  // x1 = LN(aggr@Wo + bo + x)  [fp16 only]
  k_mm_ln<<<MT64, 256, L_DYN>>>(0, bo, g1, b1n, nullptr);

  // ffn = relu(x1@Wf1 + bf1)  [fp16 out]
  k_mm_ffn1<<<dim3(MT128,8), 256, Q_DYN>>>(bf1);

  // out = LN(ffn@Wf2 + bf2 + x1)
  k_mm_ln<<<MT64, 256, L_DYN>>>(1, bf2, g2, b2n, out);

  (void)in_sizes; (void)n_in; (void)out_size;
}

// round 16
// speedup vs baseline: 1.0479x; 1.0479x over previous
#include <cuda_runtime.h>
#include <cuda_fp16.h>

#define N_ 10000
#define NPAD 10112
#define E_ 160000

typedef unsigned int uint32;

// ---------------- device scratch ---------------------------------------------
__device__ __align__(16) __half g_Qh[N_*256];
__device__ __align__(16) __half g_Kh[N_*256];
__device__ __align__(16) __half g_Vh[N_*256];
__device__ __align__(16) float g_score[E_*8];
__device__ __align__(16) __half g_xh[NPAD*256];
__device__ __align__(16) __half g_aggrh[NPAD*256];
__device__ __align__(16) __half g_x1h[NPAD*256];
__device__ __align__(16) __half g_ffn[NPAD*1024];
__device__ int   g_cnt[N_];
__device__ int   g_rowptr[N_+1];
__device__ int   g_cur[N_];
__device__ int   g_pos[E_];    // edge -> CSR slot
__device__ int   g_srcs[E_];   // CSR slot -> src node

// transposed weights, [N][K] fp16 (K contiguous)
#define OFF_Q  0u
#define OFF_K  65536u
#define OFF_V  131072u
#define OFF_P2 196608u
#define OFF_O  262144u
#define OFF_F1 327680u      /* [1024][256] */
#define OFF_F2 589824u      /* [256][1024] */
#define WT_TOTAL 851968u
__device__ __align__(16) __half g_wt[WT_TOTAL];

// ---------------- smem layouts ---------------------------------------------------
#define Q_A0 0
#define Q_A1 16384
#define Q_B0 32768
#define Q_B1 49152
#define Q_PAR 65536
#define Q_DYN 67584
// LN (M=64,N=256)
#define L_A0 0
#define L_A1 8192
#define L_B0 16384
#define L_B1 49152
#define L_PAR 81920
#define L_DYN 94208
// EDGE (M=64,N=256): full A (4 chunks) + 2 B buffers; epilogue reuses for Q/K
#define EA    0          /* 4 x 8192 = 32768 */
#define EB0   32768
#define EB1   65536
#define E_PAR 98304
#define E_DYN 110592
// epilogue Q/K staging (row stride 264 halves = 528 B)
#define QS_OFF 0
#define KS_OFF 33792

__device__ __forceinline__ uint32 smem_to_u32(const void* p){
  uint32 a;
  asm("{ .reg .u64 t; cvta.to.shared.u64 t, %1; cvt.u32.u64 %0, t; }" : "=r"(a) : "l"(p));
  return a;
}
__device__ __forceinline__ uint32 swz(int row, int c16){
  return (uint32)(row*128 + (((c16) ^ (row & 7)) << 4));
}
__device__ __forceinline__ void ldsm4(uint32* r, uint32 addr){
  asm volatile("ldmatrix.sync.aligned.m8n8.x4.shared.b16 {%0,%1,%2,%3}, [%4];"
    : "=r"(r[0]),"=r"(r[1]),"=r"(r[2]),"=r"(r[3]) : "r"(addr));
}
__device__ __forceinline__ void mma_f16(float* c, const uint32* a, uint32 b0, uint32 b1){
  asm volatile("mma.sync.aligned.m16n8k16.row.col.f32.f16.f16.f32 "
    "{%0,%1,%2,%3}, {%4,%5,%6,%7}, {%8,%9}, {%0,%1,%2,%3};"
    : "+f"(c[0]),"+f"(c[1]),"+f"(c[2]),"+f"(c[3])
    : "r"(a[0]),"r"(a[1]),"r"(a[2]),"r"(a[3]), "r"(b0),"r"(b1));
}
__device__ __forceinline__ void cpa16(uint32 dst, const void* src){
  asm volatile("cp.async.cg.shared.global [%0], [%1], 16;" :: "r"(dst), "l"(src));
}
#define CPA_COMMIT() asm volatile("cp.async.commit_group;" ::: "memory")
#define CPA_WAIT(n)  asm volatile("cp.async.wait_group %0;" :: "n"(n) : "memory")

union HU { __half h[8]; uint4 u; };

// ---------------- staging: fp16 tile via cp.async -------------------------------
template<int ROWS>
__device__ __forceinline__ void stage_tile(uint32 dstbase, const __half* src0,
                                           int Kst, int kk, int t){
  #pragma unroll
  for (int s=0; s<(ROWS>>5); s++){
    int slot = t + s*256;
    int r = slot >> 3, g = slot & 7;
    cpa16(dstbase + swz(r, g), (const void*)(src0 + (size_t)r*Kst + kk + g*8));
  }
}

// ---------------- warp MMA mainloop: warp tile 32 x 64 --------------------------
__device__ __forceinline__ void compute_chunk(uint32 sb, uint32 aoff, uint32 boff,
                                              int lane, int wm, int wn,
                                              float (&acc)[2][8][4]){
  uint32 rbA[2]; int rxA[2];
  #pragma unroll
  for (int mi=0;mi<2;mi++){
    int row = wm*32 + mi*16 + (lane&15);
    rbA[mi] = sb + aoff + row*128;
    rxA[mi] = row & 7;
  }
  int hi4 = lane>>4;
  uint32 rbB[4]; int rxB[4];
  #pragma unroll
  for (int g=0; g<4; g++){
    int n = wn*64 + g*16 + ((lane>>4)<<3) + (lane&7);
    rbB[g] = sb + boff + n*128;
    rxB[g] = n & 7;
  }
  int cB = (lane>>3)&1;
  #pragma unroll
  for (int ks=0; ks<4; ks++){
    int c16 = ks*2;
    uint32 Ah[2][4];
    #pragma unroll
    for (int mi=0;mi<2;mi++){
      uint32 off = ((uint32)((c16 + hi4) ^ rxA[mi])) << 4;
      ldsm4(Ah[mi], rbA[mi] + off);
    }
    uint32 Bh[4][4];
    #pragma unroll
    for (int g=0; g<4; g++){
      uint32 off = ((uint32)((c16 + cB) ^ rxB[g])) << 4;
      ldsm4(Bh[g], rbB[g] + off);
    }
    #pragma unroll
    for (int mi=0;mi<2;mi++){
      #pragma unroll
      for (int nn=0;nn<8;nn++)
        mma_f16(acc[mi][nn], Ah[mi], Bh[nn>>1][(nn&1)*2], Bh[nn>>1][(nn&1)*2+1]);
    }
  }
}

#define ZERO_ACC(acc) { \
  _Pragma("unroll") for (int _a=0;_a<2;_a++) \
    _Pragma("unroll") for (int _b=0;_b<8;_b++) \
      _Pragma("unroll") for (int _c=0;_c<4;_c++) (acc)[_a][_b][_c]=0.f; }

// ---------------- CSR build (count fused into prep) -----------------------------
__global__ void k_scan(){
  __shared__ int sh[1024];
  int t = threadIdx.x;
  int base = t*10;
  int loc[10]; int run=0;
  #pragma unroll
  for (int i=0;i<10;i++){ int idx=base+i; int v=(idx<N_)? g_cnt[idx]:0; loc[i]=run; run+=v; }
  sh[t]=run; __syncthreads();
  for (int off=1; off<1024; off<<=1){
    int v = (t>=off)? sh[t-off] : 0;
    __syncthreads();
    sh[t] += v;
    __syncthreads();
  }
  int pre = (t>0)? sh[t-1] : 0;
  #pragma unroll
  for (int i=0;i<10;i++){ int idx=base+i; if (idx<N_){ int p=pre+loc[i]; g_rowptr[idx]=p; g_cur[idx]=p; } }
  if (t==1023) g_rowptr[N_] = sh[1023];
}
__global__ void k_scatter(const int* __restrict__ ei){
  int e = blockIdx.x*256+threadIdx.x;
  if (e<E_){
    int d = ei[E_+e];
    int p = atomicAdd(&g_cur[d], 1);
    g_pos[e] = p;
    g_srcs[p] = ei[e];
  }
  if (e<N_) g_cnt[e]=0;
}

// ---------------- fused prep: 7 weight transposes + x fp16 + edge count ---------
__global__ void k_prep_all(
    const float* __restrict__ Wq, const float* __restrict__ Wk,
    const float* __restrict__ Wv, const float* __restrict__ Wp2,
    const float* __restrict__ Wo, const float* __restrict__ Wf1,
    const float* __restrict__ Wf2, const float* __restrict__ x,
    const int* __restrict__ ei){
  __shared__ float tile[32][33];
  int bid = blockIdx.x;
  int tx = threadIdx.x, ty = threadIdx.y;   // 32 x 8
  int t = ty*32 + tx;
  if (bid >= 2082){
    int e = (bid-2082)*256 + t;
    if (e<E_) atomicAdd(&g_cnt[ei[E_+e]], 1);
    return;
  }
  if (bid >= 832){
    size_t base = (size_t)(bid-832)*2048 + (size_t)t*8;
    float4 a = *(const float4*)(x + base);
    float4 b = *(const float4*)(x + base + 4);
    HU H;
    H.h[0]=__float2half_rn(a.x); H.h[1]=__float2half_rn(a.y);
    H.h[2]=__float2half_rn(a.z); H.h[3]=__float2half_rn(a.w);
    H.h[4]=__float2half_rn(b.x); H.h[5]=__float2half_rn(b.y);
    H.h[6]=__float2half_rn(b.z); H.h[7]=__float2half_rn(b.w);
    *(uint4*)(g_xh + base) = H.u;
    return;
  }
  const float* W; int K, N; uint32 off; int local;
  if (bid < 320){
    local = bid & 63;
    int w = bid >> 6;
    W = (w==0)?Wq:(w==1)?Wk:(w==2)?Wv:(w==3)?Wp2:Wo;
    K = 256; N = 256; off = (uint32)w*65536u;
  } else if (bid < 576){ local = bid-320; W = Wf1; K = 256;  N = 1024; off = OFF_F1; }
  else                 { local = bid-576; W = Wf2; K = 1024; N = 256;  off = OFF_F2; }
  int nkb = K/32;
  int k0 = (local % nkb)*32, n0 = (local / nkb)*32;
  #pragma unroll
  for (int i=0;i<4;i++)
    tile[ty+i*8][tx] = W[(size_t)(k0+ty+i*8)*N + n0 + tx];
  __syncthreads();
  #pragma unroll
  for (int i=0;i<4;i++){
    int n = n0 + ty + i*8, k = k0 + tx;
    g_wt[(size_t)off + (size_t)n*K + k] = __float2half_rn(tile[tx][ty+i*8]);
  }
}

// ---------------- QKV GEMMs: M=128, N=128 tile; 2-stage; fp16 out ---------------
__global__ void __launch_bounds__(256,2) k_mm_qkv(
    const float* __restrict__ bq, const float* __restrict__ bk,
    const float* __restrict__ bv){
  extern __shared__ char smem[];
  uint32 sb = smem_to_u32(smem);
  int t = threadIdx.x, lane = t&31, wid = t>>5;
  int wm = wid>>1, wn = wid&1;
  int r0 = blockIdx.x*128;
  int gemm = blockIdx.y >> 1, nh = blockIdx.y & 1;
  const __half* Bsrc = g_wt + (size_t)gemm*65536 + (size_t)nh*128*256;
  const float* bias = (gemm==0)?bq:((gemm==1)?bk:bv);
  __half* C = (gemm==0)?g_Qh:((gemm==1)?g_Kh:g_Vh);
  const __half* Asrc = g_xh + (size_t)r0*256;
  float* s_bias = (float*)(smem + Q_PAR);
  if (t < 128) s_bias[t] = bias[nh*128 + t];

  float acc[2][8][4];
  ZERO_ACC(acc);

  stage_tile<128>(sb + Q_A0, Asrc, 256, 0, t);
  stage_tile<128>(sb + Q_B0, Bsrc, 256, 0, t);
  CPA_COMMIT();
  #pragma unroll
  for (int ck=0; ck<4; ck++){
    if (ck<3){
      stage_tile<128>(sb + ((ck&1)? Q_A0:Q_A1), Asrc, 256, (ck+1)*64, t);
      stage_tile<128>(sb + ((ck&1)? Q_B0:Q_B1), Bsrc, 256, (ck+1)*64, t);
      CPA_COMMIT(); CPA_WAIT(1);
    } else { CPA_WAIT(0); }
    __syncthreads();
    compute_chunk(sb, (ck&1)?Q_A1:Q_A0, (ck&1)?Q_B1:Q_B0, lane, wm, wn, acc);
    if (ck<3) __syncthreads();
  }

  #pragma unroll
  for (int mi=0;mi<2;mi++){
    int rA = wm*32 + mi*16 + (lane>>2);
    #pragma unroll
    for (int half=0; half<2; half++){
      int row = r0 + rA + half*8;
      if (row >= N_) continue;
      #pragma unroll
      for (int ni=0;ni<8;ni++){
        int lc = wn*64 + ni*8 + (lane&3)*2;
        float v0 = acc[mi][ni][half*2+0] + s_bias[lc];
        float v1 = acc[mi][ni][half*2+1] + s_bias[lc+1];
        *(__half2*)(C + (size_t)row*256 + nh*128 + lc) = __floats2half2_rn(v0, v1);
      }
    }
  }
}

// ---------------- FFN1: M=128, N=128 tile; 2-stage; fp16 out --------------------
__global__ void __launch_bounds__(256,2) k_mm_ffn1(const float* __restrict__ bf1){
  extern __shared__ char smem[];
  uint32 sb = smem_to_u32(smem);
  int t = threadIdx.x, lane = t&31, wid = t>>5;
  int wm = wid>>1, wn = wid&1;
  int r0 = blockIdx.x*128;
  int colOff = blockIdx.y*128;
  const __half* Bsrc = g_wt + OFF_F1 + (size_t)colOff*256;
  const __half* Asrc = g_x1h + (size_t)r0*256;
  float* s_bias = (float*)(smem + Q_PAR);
  if (t < 128) s_bias[t] = bf1[colOff + t];

  float acc[2][8][4];
  ZERO_ACC(acc);

  stage_tile<128>(sb + Q_A0, Asrc, 256, 0, t);
  stage_tile<128>(sb + Q_B0, Bsrc, 256, 0, t);
  CPA_COMMIT();
  #pragma unroll
  for (int ck=0; ck<4; ck++){
    if (ck<3){
      stage_tile<128>(sb + ((ck&1)? Q_A0:Q_A1), Asrc, 256, (ck+1)*64, t);
      stage_tile<128>(sb + ((ck&1)? Q_B0:Q_B1), Bsrc, 256, (ck+1)*64, t);
      CPA_COMMIT(); CPA_WAIT(1);
    } else { CPA_WAIT(0); }
    __syncthreads();
    compute_chunk(sb, (ck&1)?Q_A1:Q_A0, (ck&1)?Q_B1:Q_B0, lane, wm, wn, acc);
    if (ck<3) __syncthreads();
  }

  #pragma unroll
  for (int mi=0;mi<2;mi++){
    int rA = wm*32 + mi*16 + (lane>>2);
    #pragma unroll
    for (int half=0; half<2; half++){
      int row = r0 + rA + half*8;
      if (row >= N_) continue;
      #pragma unroll
      for (int ni=0;ni<8;ni++){
        int lc = wn*64 + ni*8 + (lane&3)*2;
        float v0 = fmaxf(acc[mi][ni][half*2+0] + s_bias[lc],   0.f);
        float v1 = fmaxf(acc[mi][ni][half*2+1] + s_bias[lc+1], 0.f);
        *(__half2*)(g_ffn + (size_t)row*1024 + colOff + lc) = __floats2half2_rn(v0, v1);
      }
    }
  }
}

// ---------------- edge: M=64, N=256; full-A hoist; Q/K prefetch epilogue --------
__global__ void __launch_bounds__(256,2) k_mm_edge(
    const float* __restrict__ pos, const int* __restrict__ ei,
    const float* __restrict__ Wp1, const float* __restrict__ bp1,
    const float* __restrict__ bp2, const float* __restrict__ gp,
    const float* __restrict__ bpn){
  extern __shared__ char smem[];
  uint32 sb = smem_to_u32(smem);
  int t = threadIdx.x, lane = t&31, wid = t>>5;
  int wm = wid>>2, wn = wid&3;
  int e0 = blockIdx.x*64;

  float* s_w1   = (float*)(smem + E_PAR);   // 768
  float* s_b1   = s_w1 + 768;               // 256
  float* s_p2   = s_b1 + 256;               // 256
  float* s_gp   = s_p2 + 256;               // 256
  float* s_bn   = s_gp + 256;               // 256
  float* s_dp   = s_bn + 256;               // 192
  float* s_part = s_dp + 192;               // 512
  int*   s_nd   = (int*)(s_part + 512);     // 192 ints (src, dst, pos)

  // stage B chunk 0 first so it flies during param load + A generation
  stage_tile<256>(sb + EB0, g_wt + OFF_P2, 256, 0, t);
  CPA_COMMIT();

  s_w1[t]     = Wp1[t];
  s_w1[256+t] = Wp1[256+t];
  s_w1[512+t] = Wp1[512+t];
  s_b1[t] = bp1[t]; s_p2[t] = bp2[t]; s_gp[t] = gp[t]; s_bn[t] = bpn[t];
  if (t < 64){
    int e = e0 + t;
    int sn = ei[e], dn = ei[E_+e];
    s_nd[t] = sn; s_nd[64+t] = dn; s_nd[128+t] = g_pos[e];
    s_dp[t*3+0] = pos[dn*3+0]-pos[sn*3+0];
    s_dp[t*3+1] = pos[dn*3+1]-pos[sn*3+1];
    s_dp[t*3+2] = pos[dn*3+2]-pos[sn*3+2];
  }
  __syncthreads();

  int rr = t>>2, q4 = t&3;
  float dx = s_dp[rr*3+0], dy = s_dp[rr*3+1], dz = s_dp[rr*3+2];

  // generate ALL 4 A chunks up front (overlaps with B0 cp.async flight)
  #pragma unroll
  for (int ck=0; ck<4; ck++){
    int kk = ck*64;
    #pragma unroll
    for (int half=0; half<2; half++){
      HU H;
      #pragma unroll
      for (int j=0; j<8; j++){
        int c = kk + q4*16 + half*8 + j;
        float v = fmaf(dz, s_w1[512+c], fmaf(dy, s_w1[256+c], fmaf(dx, s_w1[c], s_b1[c])));
        H.h[j] = __float2half_rn(fmaxf(v, 0.f));
      }
      *(uint4*)(smem + EA + ck*8192 + swz(rr, q4*2 + half)) = H.u;
    }
  }

  float acc[2][8][4];
  ZERO_ACC(acc);

  #pragma unroll
  for (int ck=0; ck<4; ck++){
    if (ck<3){
      stage_tile<256>(sb + ((ck&1)? EB0:EB1), g_wt + OFF_P2, 256, (ck+1)*64, t);
      CPA_COMMIT(); CPA_WAIT(1);
    } else { CPA_WAIT(0); }
    __syncthreads();
    compute_chunk(sb, EA + ck*8192, (ck&1)?EB1:EB0, lane, wm, wn, acc);
    __syncthreads();
  }

  // mainloop done; EA/EB smem is free. Prefetch the 64 Q(dst) rows and 64
  // K(src) rows into smem via cp.async — overlaps with pass-1 register work.
  // Layout: 264-half (528B) row stride -> conflict-free pass-2 reads.
  #pragma unroll
  for (int s=0; s<16; s++){
    int slot = t + s*256;
    int mat = slot >> 11;          // 0: Q(dst), 1: K(src)
    int rem = slot & 2047;
    int row = rem >> 5, seg = rem & 31;
    int node = mat ? s_nd[row] : s_nd[64+row];
    const __half* src = (mat ? g_Kh : g_Qh) + (size_t)node*256 + seg*8;
    cpa16(sb + (mat ? KS_OFF : QS_OFF) + row*528 + seg*16, src);
  }
  CPA_COMMIT();

  // pass 1: vals = acc + bp2; per-row partial LN stats (register/shfl only)
  #pragma unroll
  for (int mi=0;mi<2;mi++){
    int rA = wm*32 + mi*16 + (lane>>2);
    #pragma unroll
    for (int half=0; half<2; half++){
      int rl = rA + half*8;
      float s1=0.f, s2=0.f;
      #pragma unroll
      for (int ni=0;ni<8;ni++){
        int col = wn*64 + ni*8 + (lane&3)*2;
        float v0 = acc[mi][ni][half*2+0] + s_p2[col];
        float v1 = acc[mi][ni][half*2+1] + s_p2[col+1];
        acc[mi][ni][half*2+0] = v0;
        acc[mi][ni][half*2+1] = v1;
        s1 += v0 + v1;
        s2 = fmaf(v0, v0, fmaf(v1, v1, s2));
      }
      s1 += __shfl_xor_sync(0xffffffffu, s1, 1);
      s1 += __shfl_xor_sync(0xffffffffu, s1, 2);
      s2 += __shfl_xor_sync(0xffffffffu, s2, 1);
      s2 += __shfl_xor_sync(0xffffffffu, s2, 2);
      if ((lane&3)==0){ s_part[(rl*4+wn)*2] = s1; s_part[(rl*4+wn)*2+1] = s2; }
    }
  }
  CPA_WAIT(0);
  __syncthreads();

  // pass 2: LN + per-head scores (Q/K now in smem, conflict-free)
  const __half* Qs = (const __half*)(smem + QS_OFF);
  const __half* Ks = (const __half*)(smem + KS_OFF);
  const float SC = 0.17677669529663688f;  // 1/sqrt(32)
  #pragma unroll
  for (int mi=0;mi<2;mi++){
    int rA = wm*32 + mi*16 + (lane>>2);
    #pragma unroll
    for (int half=0; half<2; half++){
      int rl = rA + half*8;
      float s1 = s_part[(rl*4+0)*2] + s_part[(rl*4+1)*2]
               + s_part[(rl*4+2)*2] + s_part[(rl*4+3)*2];
      float s2 = s_part[(rl*4+0)*2+1] + s_part[(rl*4+1)*2+1]
               + s_part[(rl*4+2)*2+1] + s_part[(rl*4+3)*2+1];
      float m = s1*(1.f/256.f);
      float rstd = rsqrtf(fmaxf(s2*(1.f/256.f) - m*m, 0.f) + 1e-5f);
      int pp = s_nd[128+rl];
      const __half* Qp = Qs + rl*264;
      const __half* Kp = Ks + rl*264;
      #pragma unroll
      for (int h=0; h<2; h++){
        float partial = 0.f;
        #pragma unroll
        for (int nio=0; nio<4; nio++){
          int ni = h*4 + nio;
          int col = wn*64 + ni*8 + (lane&3)*2;
          float2 qv = __half22float2(*(const __half2*)(Qp + col));
          float2 kv = __half22float2(*(const __half2*)(Kp + col));
          float pe0 = (acc[mi][ni][half*2+0]-m)*rstd*s_gp[col]   + s_bn[col];
          float pe1 = (acc[mi][ni][half*2+1]-m)*rstd*s_gp[col+1] + s_bn[col+1];
          partial = fmaf(qv.x, kv.x + pe0, partial);
          partial = fmaf(qv.y, kv.y + pe1, partial);
        }
        partial += __shfl_xor_sync(0xffffffffu, partial, 1);
        partial += __shfl_xor_sync(0xffffffffu, partial, 2);
        if ((lane&3)==0)
          g_score[(size_t)pp*8 + wn*2 + h] = partial*SC;
      }
    }
  }
}

// ---------------- segment softmax + weighted aggregation (128 thr, half2 V) -----
__global__ void __launch_bounds__(128) k_aggr(){
  int n = blockIdx.x;
  int beg = g_rowptr[n], end = g_rowptr[n+1];
  int t = threadIdx.x, lane = t&31, w = t>>5;   // 4 warps
  __shared__ float s_mx[8], s_rs[8];
  __shared__ float s_at[128*8];
  __shared__ int   s_sc[128];

  #pragma unroll
  for (int hh=0; hh<2; hh++){
    int h = w*2 + hh;
    float mx = -3.0e38f;
    for (int i=beg+lane; i<end; i+=32)
      mx = fmaxf(mx, g_score[(size_t)i*8+h]);
    #pragma unroll
    for (int o=16;o>0;o>>=1) mx = fmaxf(mx, __shfl_xor_sync(0xffffffffu, mx, o));
    float s=0.f;
    for (int i=beg+lane; i<end; i+=32)
      s += __expf(g_score[(size_t)i*8+h]-mx);
    #pragma unroll
    for (int o=16;o>0;o>>=1) s += __shfl_xor_sync(0xffffffffu, s, o);
    if (lane==0){ s_mx[h]=mx; s_rs[h]=1.f/(s+1e-16f); }
  }
  __syncthreads();

  float ax=0.f, ay=0.f;
  int c0col = t*2;
  int h = c0col >> 5;
  for (int c0=beg; c0<end; c0+=128){
    int cn = min(128, end-c0);
    for (int j=t; j<cn*8; j+=128){
      int i=j>>3, hh=j&7;
      s_at[i*8+hh] = __expf(g_score[(size_t)(c0+i)*8+hh]-s_mx[hh])*s_rs[hh];
      if (hh==0) s_sc[i] = g_srcs[c0+i];
    }
    __syncthreads();
    for (int i=0;i<cn;i++){
      float a = s_at[i*8+h];
      float2 v = __half22float2(*(const __half2*)(g_Vh + (size_t)s_sc[i]*256 + c0col));
      ax = fmaf(a, v.x, ax);
      ay = fmaf(a, v.y, ay);
    }
    __syncthreads();
  }
  *(__half2*)(g_aggrh + (size_t)n*256 + c0col) = __floats2half2_rn(ax, ay);
}

// ---------------- GEMM + LN (Wo / FFN2): M=64, N=256; fp16 residuals ------------
__global__ void __launch_bounds__(256,2) k_mm_ln(int mode,
    const float* __restrict__ bias,
    const float* __restrict__ gam, const float* __restrict__ bet,
    float* __restrict__ outp){
  extern __shared__ char smem[];
  uint32 sb = smem_to_u32(smem);
  int t = threadIdx.x, lane = t&31, wid = t>>5;
  int wm = wid>>2, wn = wid&3;
  int r0 = blockIdx.x*64;
  const __half* res; int K; const __half* Bsrc; const __half* Asrc; int Kst;
  if (mode==0){
    res = g_xh;  K=256;  Bsrc=g_wt+OFF_O;
    Asrc = g_aggrh + (size_t)r0*256; Kst=256;
  } else {
    res = g_x1h; K=1024; Bsrc=g_wt+OFF_F2;
    Asrc = g_ffn + (size_t)r0*1024; Kst=1024;
  }

  float* s_bias = (float*)(smem + L_PAR);
  float* s_g    = s_bias + 256;
  float* s_b    = s_g + 256;
  float* s_part = s_b + 256;
  s_bias[t] = bias[t]; s_g[t] = gam[t]; s_b[t] = bet[t];

  float acc[2][8][4];
  ZERO_ACC(acc);

  int nchunks = K/64;
  stage_tile<64>(sb + L_A0, Asrc, Kst, 0, t);
  stage_tile<256>(sb + L_B0, Bsrc, K, 0, t);
  CPA_COMMIT();
  for (int ck=0; ck<nchunks; ck++){
    if (ck+1 < nchunks){
      stage_tile<64>(sb + ((ck&1)? L_A0:L_A1), Asrc, Kst, (ck+1)*64, t);
      stage_tile<256>(sb + ((ck&1)? L_B0:L_B1), Bsrc, K, (ck+1)*64, t);
      CPA_COMMIT(); CPA_WAIT(1);
    } else { CPA_WAIT(0); }
    __syncthreads();
    compute_chunk(sb, (ck&1)?L_A1:L_A0, (ck&1)?L_B1:L_B0, lane, wm, wn, acc);
    if (ck+1 < nchunks) __syncthreads();
  }

  #pragma unroll
  for (int mi=0;mi<2;mi++){
    int rA = wm*32 + mi*16 + (lane>>2);
    #pragma unroll
    for (int half=0; half<2; half++){
      int rl = rA + half*8;
      int row = r0 + rl;
      bool ok = row < N_;
      float s1=0.f, s2=0.f;
      #pragma unroll
      for (int ni=0;ni<8;ni++){
        int col = wn*64 + ni*8 + (lane&3)*2;
        float2 rv = ok ? __half22float2(*(const __half2*)(res + (size_t)row*256 + col))
                       : make_float2(0.f, 0.f);
        float v0 = acc[mi][ni][half*2+0] + s_bias[col]   + rv.x;
        float v1 = acc[mi][ni][half*2+1] + s_bias[col+1] + rv.y;
        acc[mi][ni][half*2+0] = v0;
        acc[mi][ni][half*2+1] = v1;
        s1 += v0 + v1;
        s2 = fmaf(v0, v0, fmaf(v1, v1, s2));
      }
      s1 += __shfl_xor_sync(0xffffffffu, s1, 1);
      s1 += __shfl_xor_sync(0xffffffffu, s1, 2);
      s2 += __shfl_xor_sync(0xffffffffu, s2, 1);
      s2 += __shfl_xor_sync(0xffffffffu, s2, 2);
      if ((lane&3)==0){ s_part[(rl*4+wn)*2] = s1; s_part[(rl*4+wn)*2+1] = s2; }
    }
  }
  __syncthreads();

  #pragma unroll
  for (int mi=0;mi<2;mi++){
    int rA = wm*32 + mi*16 + (lane>>2);
    #pragma unroll
    for (int half=0; half<2; half++){
      int rl = rA + half*8;
      int row = r0 + rl;
      if (row >= N_) continue;
      float s1 = s_part[(rl*4+0)*2] + s_part[(rl*4+1)*2]
               + s_part[(rl*4+2)*2] + s_part[(rl*4+3)*2];
      float s2 = s_part[(rl*4+0)*2+1] + s_part[(rl*4+1)*2+1]
               + s_part[(rl*4+2)*2+1] + s_part[(rl*4+3)*2+1];
      float m = s1*(1.f/256.f);
      float rstd = rsqrtf(fmaxf(s2*(1.f/256.f) - m*m, 0.f) + 1e-5f);
      #pragma unroll
      for (int ni=0;ni<8;ni++){
        int col = wn*64 + ni*8 + (lane&3)*2;
        float o0 = (acc[mi][ni][half*2+0]-m)*rstd*s_g[col]   + s_b[col];
        float o1 = (acc[mi][ni][half*2+1]-m)*rstd*s_g[col+1] + s_b[col+1];
        if (mode==0){
          *(__half2*)(g_x1h + (size_t)row*256 + col) = __floats2half2_rn(o0, o1);
        } else {
          *(float2*)(outp + (size_t)row*256 + col) = make_float2(o0, o1);
        }
      }
    }
  }
}

// ---------------- launch ---------------------------------------------------------
extern "C" void kernel_launch(void* const* d_in, const int* in_sizes, int n_in,
                              void* d_out, int out_size){
  const float* x    = (const float*)d_in[0];
  const float* pos  = (const float*)d_in[1];
  const int*   ei   = (const int*)  d_in[2];
  const float* Wq   = (const float*)d_in[3];
  const float* bq   = (const float*)d_in[4];
  const float* Wk   = (const float*)d_in[5];
  const float* bk   = (const float*)d_in[6];
  const float* Wv   = (const float*)d_in[7];
  const float* bv   = (const float*)d_in[8];
  const float* Wp1  = (const float*)d_in[9];
  const float* bp1  = (const float*)d_in[10];
  const float* Wp2  = (const float*)d_in[11];
  const float* bp2  = (const float*)d_in[12];
  const float* gp   = (const float*)d_in[13];
  const float* bp   = (const float*)d_in[14];
  const float* Wo   = (const float*)d_in[15];
  const float* bo   = (const float*)d_in[16];
  const float* g1   = (const float*)d_in[17];
  const float* b1n  = (const float*)d_in[18];
  const float* Wf1  = (const float*)d_in[19];
  const float* bf1  = (const float*)d_in[20];
  const float* Wf2  = (const float*)d_in[21];
  const float* bf2  = (const float*)d_in[22];
  const float* g2   = (const float*)d_in[23];
  const float* b2n  = (const float*)d_in[24];
  float* out = (float*)d_out;

  cudaFuncSetAttribute(k_mm_qkv,  cudaFuncAttributeMaxDynamicSharedMemorySize, Q_DYN);
  cudaFuncSetAttribute(k_mm_ffn1, cudaFuncAttributeMaxDynamicSharedMemorySize, Q_DYN);
  cudaFuncSetAttribute(k_mm_edge, cudaFuncAttributeMaxDynamicSharedMemorySize, E_DYN);
  cudaFuncSetAttribute(k_mm_ln,   cudaFuncAttributeMaxDynamicSharedMemorySize, L_DYN);

  const int MT128 = (N_ + 127) / 128;  // 79
  const int MT64  = (N_ + 63) / 64;    // 157
  const int ET    = E_ / 64;           // 2500

  // fused prep: 7 weight transposes + x->fp16 + edge count
  k_prep_all<<<2707, dim3(32,8)>>>(Wq, Wk, Wv, Wp2, Wo, Wf1, Wf2, x, ei);

  // CSR: scan + scatter (g_cnt re-zeroed by k_scatter tail each run)
  k_scan   <<<1, 1024>>>();
  k_scatter<<<(E_+255)/256, 256>>>(ei);

  // Q/K/V  (3 gemms x 2 n-halves)  [fp16 out]
  k_mm_qkv<<<dim3(MT128,6), 256, Q_DYN>>>(bq, bk, bv);

  // edge: pe-MLP GEMM + LN + scores (CSR-ordered, Q/K smem prefetch)
  k_mm_edge<<<ET, 256, E_DYN>>>(pos, ei, Wp1, bp1, bp2, gp, bp);

  // segment softmax + aggregation [fp16 out]
  k_aggr<<<N_, 128>>>();

  // x1 = LN(aggr@Wo + bo + x)  [fp16 only]
  k_mm_ln<<<MT64, 256, L_DYN>>>(0, bo, g1, b1n, nullptr);

  // ffn = relu(x1@Wf1 + bf1)  [fp16 out]
  k_mm_ffn1<<<dim3(MT128,8), 256, Q_DYN>>>(bf1);

  // out = LN(ffn@Wf2 + bf2 + x1)
  k_mm_ln<<<MT64, 256, L_DYN>>>(1, bf2, g2, b2n, out);

  (void)in_sizes; (void)n_in; (void)out_size;
}